// round 12
// baseline (speedup 1.0000x reference)
#include <cuda_runtime.h>
#include <cuda_bf16.h>
#include <cstdint>
#include <cstddef>

// Problem dims (fixed by the reference)
#define BB   64
#define TT   4096
#define DE   512
#define DA   256

// ---------------- scratch (device globals; no allocation in kernel_launch) ----------------
__device__ __nv_bfloat16 g_wk_bf[DA * DE];                  // 256 KB
__device__ float         g_qpk[BB * DA];                    // q + Wq_b + Wk_b
__device__ float         g_scores2[2][(size_t)BB * TT];     // per-N-half partial scores
__device__ float         g_ctx_part[8][(size_t)BB * DE];    // T-split partial ctx
__device__ float         g_psum[8][BB];                     // T-split partial exp-sums

// ---------------- PTX helpers (compute_103-safe: no tcgen05/TMEM) ----------------
__device__ __forceinline__ uint32_t smem_u32(const void* p) {
    uint32_t a;
    asm("{ .reg .u64 t; cvta.to.shared.u64 t, %1; cvt.u32.u64 %0, t; }" : "=r"(a) : "l"(p));
    return a;
}
__device__ __forceinline__ void cp_async16(uint32_t dst, const void* src) {
    asm volatile("cp.async.cg.shared.global [%0], [%1], 16;" :: "r"(dst), "l"(src) : "memory");
}
__device__ __forceinline__ void cp_commit() {
    asm volatile("cp.async.commit_group;" ::: "memory");
}
template <int N>
__device__ __forceinline__ void cp_wait() {
    asm volatile("cp.async.wait_group %0;" :: "n"(N) : "memory");
}
__device__ __forceinline__ void ldmatrix_x4(uint32_t* r, uint32_t addr) {
    asm volatile("ldmatrix.sync.aligned.m8n8.x4.shared.b16 {%0,%1,%2,%3}, [%4];"
                 : "=r"(r[0]), "=r"(r[1]), "=r"(r[2]), "=r"(r[3]) : "r"(addr));
}
__device__ __forceinline__ void ldmatrix_x2(uint32_t* r, uint32_t addr) {
    asm volatile("ldmatrix.sync.aligned.m8n8.x2.shared.b16 {%0,%1}, [%2];"
                 : "=r"(r[0]), "=r"(r[1]) : "r"(addr));
}
__device__ __forceinline__ void mma16816(float* c, const uint32_t* a, const uint32_t* b) {
    asm volatile(
        "mma.sync.aligned.m16n8k16.row.col.f32.bf16.bf16.f32 "
        "{%0,%1,%2,%3}, {%4,%5,%6,%7}, {%8,%9}, {%0,%1,%2,%3};"
        : "+f"(c[0]), "+f"(c[1]), "+f"(c[2]), "+f"(c[3])
        : "r"(a[0]), "r"(a[1]), "r"(a[2]), "r"(a[3]), "r"(b[0]), "r"(b[1]));
}
__device__ __forceinline__ float tanh_approx(float x) {
    float y;
    asm("tanh.approx.f32 %0, %1;" : "=f"(y) : "f"(x));
    return y;
}
__device__ __forceinline__ uint32_t pack_bf16x2(float lo, float hi) {
    __nv_bfloat162 p = __floats2bfloat162_rn(lo, hi);
    return *reinterpret_cast<uint32_t*>(&p);
}

// SW128 swizzle (Swizzle<3,4,3>) on tile-local byte offsets, rows = 128B.
#define SWZ(o) ((o) ^ (((o) >> 3) & 0x70))

// ---------------- kernel 1: f32 -> bf16 convert (Wk only) ----------------
__global__ void convert_kernel(const float* __restrict__ src, __nv_bfloat16* __restrict__ dst, long n4) {
    long i = (long)blockIdx.x * blockDim.x + threadIdx.x;
    if (i >= n4) return;
    float4 v = reinterpret_cast<const float4*>(src)[i];
    uint2 o;
    o.x = pack_bf16x2(v.x, v.y);
    o.y = pack_bf16x2(v.z, v.w);
    reinterpret_cast<uint2*>(dst)[i] = o;
}

// ---------------- kernel 2: qpk[b,a] = h_dec[b]·Wq[a] + Wq_b[a] + Wk_b[a] ----------------
__global__ void qpk_kernel(const float* __restrict__ hdec, const float* __restrict__ Wq,
                           const float* __restrict__ Wqb, const float* __restrict__ Wkb,
                           float* __restrict__ qpk) {
    int b = blockIdx.x;
    int a = threadIdx.x;  // 256
    __shared__ float h[DE];
    for (int e = threadIdx.x; e < DE; e += 256) h[e] = hdec[b * DE + e];
    __syncthreads();
    const float* w = Wq + (size_t)a * DE;
    float acc = 0.f;
#pragma unroll 8
    for (int e = 0; e < DE; e++) acc = fmaf(h[e], w[e], acc);
    qpk[b * DA + a] = acc + Wqb[a] + Wkb[a];
}

// ---------------- kernel 3: mma.sync GEMM + fused f32->bf16 A-convert + score epilogue ----------------
// CTA tile: M=128, N=128 (half of DA), K=512 in 8 chunks of 64.
// Single-sync double-buffer, race-free ordering:
//   top of iter: cp_wait<0> (drain B(cur)); __syncthreads (publish A/B(cur), retire reads of nxt);
//   then issueB(kc+1,nxt) + ldgA8(kc+1)  [safe: all reads of nxt retired by the sync];
//   4 MMA k-steps on cur; stsA8(nxt) at bottom.
#define SM_PART   0
#define SM_V      2048
#define SM_Q      2560
#define SM_A(st)  (4096 + (st) * 16384)
#define SM_B(st)  (36864 + (st) * 16384)
#define GEMM_SMEM 69632

__global__ void __launch_bounds__(256, 2) gemm_score_kernel(
    const float* __restrict__ A,            // [B*T, 512] f32 (h_enc)
    const __nv_bfloat16* __restrict__ Bm,   // [256, 512] bf16 (Wk)
    const float* __restrict__ qpk,
    const float* __restrict__ v_w,
    float* __restrict__ sc2) {              // [2][B*T]
    extern __shared__ char smem[];
    uint32_t sb = smem_u32(smem);
    int tid = threadIdx.x;
    int wid = tid >> 5, lane = tid & 31;
    int wm = wid >> 2, wn = wid & 3;
    int g = lane >> 2, tig = lane & 3;

    int nh = blockIdx.x & 1;
    int mt = (blockIdx.x >> 1) & 31;
    int b  = blockIdx.x >> 6;
    int t0 = mt << 7;
    size_t m0 = ((size_t)b * 32 + mt) * 128;

    if (tid < 128) {
        ((float*)(smem + SM_V))[tid] = v_w[nh * 128 + tid];
        ((float*)(smem + SM_Q))[tid] = qpk[b * DA + (nh * 128 + tid)];
    }

    const __nv_bfloat16* Bh = Bm + (size_t)(nh * 128) * DE;
    const float* Abase = A + m0 * DE;

    // A geometry: chunk = 128 rows x 64 f32; 256 threads x 8 float4 each.
    int arow0 = tid >> 4;
    int acol4 = tid & 15;
    uint32_t asw[8];
#pragma unroll
    for (int i = 0; i < 8; i++)
        asw[i] = (uint32_t)SWZ((arow0 + i * 16) * 128 + acol4 * 8);

    auto ldgA8 = [&](int kc, float4* st) {
        const float4* src = (const float4*)(Abase + (size_t)kc * 64);
#pragma unroll
        for (int i = 0; i < 8; i++) {
            int row = arow0 + i * 16;
            st[i] = src[(size_t)row * 128 + acol4];
        }
    };
    auto stsA8 = [&](int stg, const float4* st) {
        char* dst = smem + SM_A(stg);
#pragma unroll
        for (int i = 0; i < 8; i++) {
            uint2 o;
            o.x = pack_bf16x2(st[i].x, st[i].y);
            o.y = pack_bf16x2(st[i].z, st[i].w);
            *reinterpret_cast<uint2*>(dst + asw[i]) = o;
        }
    };
    auto issueB = [&](int kc, int stg) {
        uint32_t bS = sb + SM_B(stg);
        const __nv_bfloat16* bb = Bh + kc * 64;
#pragma unroll
        for (int i = 0; i < 4; i++) {
            int c = tid + i * 256;
            int row = c >> 3, cc = c & 7;
            cp_async16(bS + SWZ(row * 128 + cc * 16), bb + (size_t)row * DE + cc * 8);
        }
        cp_commit();
    };

    float acc[4][4][4];
#pragma unroll
    for (int mi = 0; mi < 4; mi++)
#pragma unroll
        for (int ni = 0; ni < 4; ni++)
#pragma unroll
            for (int e = 0; e < 4; e++) acc[mi][ni][e] = 0.f;

    int arow = wm * 64 + (lane & 15);
    int acb  = lane >> 4;
    int brow = wn * 32 + (lane & 7);
    int bkb  = (lane >> 3) & 1;

    // ---- prologue: stage 0 staged (B in flight, A converted+stored) ----
    {
        issueB(0, 0);                 // outstanding: {B0}
        float4 st[8];
        ldgA8(0, st);
        stsA8(0, st);
    }

#pragma unroll 1
    for (int kc = 0; kc < 8; kc++) {
        int cur = kc & 1, nxt = cur ^ 1;
        cp_wait<0>();                 // drain B(cur) (only group outstanding)
        __syncthreads();              // publish A/B(cur); all reads of stage nxt retired

        float4 st[8];
        if (kc < 7) {
            issueB(kc + 1, nxt);      // safe post-sync: nxt no longer being read
            ldgA8(kc + 1, st);        // LDG spans the MMA loop below
        }

        uint32_t aS = sb + SM_A(cur), bS = sb + SM_B(cur);
#pragma unroll
        for (int ks = 0; ks < 4; ks++) {
            uint32_t af[4][4], bf_[4][2];
#pragma unroll
            for (int mi = 0; mi < 4; mi++)
                ldmatrix_x4(af[mi], aS + SWZ((arow + mi * 16) * 128 + ks * 32 + acb * 16));
#pragma unroll
            for (int ni = 0; ni < 4; ni++)
                ldmatrix_x2(bf_[ni], bS + SWZ((brow + ni * 8) * 128 + ks * 32 + bkb * 16));
#pragma unroll
            for (int mi = 0; mi < 4; mi++)
#pragma unroll
                for (int ni = 0; ni < 4; ni++)
                    mma16816(acc[mi][ni], af[mi], bf_[ni]);
        }
        if (kc < 7)
            stsA8(nxt, st);           // convert + store A(kc+1); published by next iter's sync
    }
    __syncthreads();                  // retire MMA smem reads before s_part reuse

    // ---- epilogue: partial score = sum over this half's a of v*tanh(qpk + k) ----
    const float* sv = (const float*)(smem + SM_V);
    const float* sq = (const float*)(smem + SM_Q);
    float* s_part = (float*)(smem + SM_PART);

#pragma unroll
    for (int mi = 0; mi < 4; mi++) {
        float plo = 0.f, phi = 0.f;
#pragma unroll
        for (int ni = 0; ni < 4; ni++) {
            int n = wn * 32 + ni * 8 + tig * 2;
            float v0 = sv[n], v1 = sv[n + 1], q0 = sq[n], q1 = sq[n + 1];
            plo = fmaf(v0, tanh_approx(q0 + acc[mi][ni][0]), plo);
            plo = fmaf(v1, tanh_approx(q1 + acc[mi][ni][1]), plo);
            phi = fmaf(v0, tanh_approx(q0 + acc[mi][ni][2]), phi);
            phi = fmaf(v1, tanh_approx(q1 + acc[mi][ni][3]), phi);
        }
        plo += __shfl_xor_sync(~0u, plo, 1);
        plo += __shfl_xor_sync(~0u, plo, 2);
        phi += __shfl_xor_sync(~0u, phi, 1);
        phi += __shfl_xor_sync(~0u, phi, 2);
        if (tig == 0) {
            int row = wm * 64 + mi * 16 + g;
            s_part[wn * 128 + row] = plo;
            s_part[wn * 128 + row + 8] = phi;
        }
    }
    __syncthreads();
    if (tid < 128) {
        float s = s_part[tid] + s_part[128 + tid] + s_part[256 + tid] + s_part[384 + tid];
        sc2[(size_t)nh * BB * TT + (size_t)b * TT + t0 + tid] = s;
    }
}

// ---------------- kernel 4: fused exp/mask + partial ctx over T-chunks ----------------
__global__ void ctx_part_kernel(const float* __restrict__ henc, const float* __restrict__ sc2,
                                const void* __restrict__ maskp,
                                float* __restrict__ w, float* __restrict__ part,
                                float* __restrict__ psum) {
    int b = blockIdx.y;
    int tc = blockIdx.z;
    int e = blockIdx.x * 256 + threadIdx.x;
    int tid = threadIdx.x;
    __shared__ float ws[512];
    __shared__ float red[8];
    __shared__ int is_i32_sh;

    if (tid == 0) {
        // mask dtype auto-detect: int32 0/1 vs 1-byte bool (see R5 note)
        const uint32_t* mw = (const uint32_t*)maskp;
        int ok = 1;
        for (int i = 0; i < 64; i++)
            if (mw[i] > 1u) { ok = 0; break; }
        is_i32_sh = ok;
    }
    __syncthreads();
    int is_i32 = is_i32_sh;
    const int* mi32 = (const int*)maskp;
    const unsigned char* mu8 = (const unsigned char*)maskp;

    const float* s0 = sc2 + (size_t)b * TT + tc * 512;
    const float* s1 = sc2 + (size_t)BB * TT + (size_t)b * TT + tc * 512;
    float local = 0.f;
    for (int t = tid; t < 512; t += 256) {
        size_t idx = (size_t)b * TT + tc * 512 + t;
        bool mv = is_i32 ? (mi32[idx] != 0) : (mu8[idx] != 0);
        float p = mv ? __expf(s0[t] + s1[t]) : 0.f;
        ws[t] = p;
        local += p;
    }
    __syncthreads();

    if (blockIdx.x == 0) {
        for (int t = tid; t < 512; t += 256) w[(size_t)b * TT + tc * 512 + t] = ws[t];
#pragma unroll
        for (int o = 16; o; o >>= 1) local += __shfl_xor_sync(~0u, local, o);
        if ((tid & 31) == 0) red[tid >> 5] = local;
        __syncthreads();
        if (tid == 0) {
            float s = 0.f;
#pragma unroll
            for (int i = 0; i < 8; i++) s += red[i];
            psum[tc * BB + b] = s;
        }
    }

    // 4 independent accumulators: break the FMA dependency chain, raise load MLP.
    const float* base = henc + (size_t)b * TT * DE + (size_t)tc * 512 * DE + e;
    float a0 = 0.f, a1 = 0.f, a2 = 0.f, a3 = 0.f;
#pragma unroll 4
    for (int t = 0; t < 512; t += 4) {
        a0 = fmaf(ws[t + 0], base[(size_t)(t + 0) * DE], a0);
        a1 = fmaf(ws[t + 1], base[(size_t)(t + 1) * DE], a1);
        a2 = fmaf(ws[t + 2], base[(size_t)(t + 2) * DE], a2);
        a3 = fmaf(ws[t + 3], base[(size_t)(t + 3) * DE], a3);
    }
    part[((size_t)tc * BB + b) * DE + e] = (a0 + a1) + (a2 + a3);
}

// ---------------- kernel 5: finalize — normalize ctx and w ----------------
__global__ void finalize_kernel(const float* __restrict__ part, const float* __restrict__ psum,
                                float* __restrict__ ctx, float* __restrict__ w) {
    int b = blockIdx.x;
    int tid = threadIdx.x;  // 512
    __shared__ float invS;
    if (tid == 0) {
        float s = 0.f;
#pragma unroll
        for (int p = 0; p < 8; p++) s += psum[p * BB + b];
        invS = 1.f / s;
    }
    __syncthreads();
    float inv = invS;
    {
        float s = 0.f;
#pragma unroll
        for (int p = 0; p < 8; p++) s += part[((size_t)p * BB + b) * DE + tid];
        ctx[(size_t)b * DE + tid] = s * inv;
    }
    for (int t = tid; t < TT; t += 512)
        w[(size_t)b * TT + t] *= inv;
}

// ---------------- host launcher ----------------
extern "C" void kernel_launch(void* const* d_in, const int* in_sizes, int n_in,
                              void* d_out, int out_size) {
    const float* h_enc = (const float*)d_in[0];
    const float* h_dec = (const float*)d_in[1];
    const float* Wq_w  = (const float*)d_in[2];
    const float* Wq_b  = (const float*)d_in[3];
    const float* Wk_w  = (const float*)d_in[4];
    const float* Wk_b  = (const float*)d_in[5];
    const float* v_w   = (const float*)d_in[6];
    const void*  mask  = (const void*)d_in[7];

    float* out = (float*)d_out;
    float* ctx = out;                 // [B, 512]
    float* w   = out + BB * DE;       // [B, 4096]

    void *p_wk, *p_qpk, *p_sc2, *p_part, *p_psum;
    cudaGetSymbolAddress(&p_wk, g_wk_bf);
    cudaGetSymbolAddress(&p_qpk, g_qpk);
    cudaGetSymbolAddress(&p_sc2, g_scores2);
    cudaGetSymbolAddress(&p_part, g_ctx_part);
    cudaGetSymbolAddress(&p_psum, g_psum);

    cudaFuncSetAttribute(gemm_score_kernel, cudaFuncAttributeMaxDynamicSharedMemorySize, GEMM_SMEM);

    convert_kernel<<<(DA * DE / 4) / 256, 256>>>(Wk_w, (__nv_bfloat16*)p_wk, DA * DE / 4);
    qpk_kernel<<<BB, 256>>>(h_dec, Wq_w, Wq_b, Wk_b, (float*)p_qpk);
    gemm_score_kernel<<<BB * 32 * 2, 256, GEMM_SMEM>>>(
        h_enc, (const __nv_bfloat16*)p_wk,
        (const float*)p_qpk, v_w, (float*)p_sc2);
    ctx_part_kernel<<<dim3(2, BB, 8), 256>>>(h_enc, (const float*)p_sc2, mask,
                                             w, (float*)p_part, (float*)p_psum);
    finalize_kernel<<<BB, 512>>>((const float*)p_part, (const float*)p_psum, ctx, w);
}

// round 13
// speedup vs baseline: 1.0674x; 1.0674x over previous
#include <cuda_runtime.h>
#include <cuda_bf16.h>
#include <cstdint>
#include <cstddef>

// Problem dims (fixed by the reference)
#define BB   64
#define TT   4096
#define DE   512
#define DA   256

// ---------------- scratch (device globals; no allocation in kernel_launch) ----------------
__device__ __nv_bfloat16 g_wk_bf[DA * DE];                  // 256 KB
__device__ float         g_qpk[BB * DA];                    // q + Wq_b + Wk_b
__device__ float         g_scores[(size_t)BB * TT];         // full additive scores
__device__ float         g_ctx_part[8][(size_t)BB * DE];    // T-split partial ctx
__device__ float         g_psum[8][BB];                     // T-split partial exp-sums

// ---------------- PTX helpers (compute_103-safe: no tcgen05/TMEM) ----------------
__device__ __forceinline__ uint32_t smem_u32(const void* p) {
    uint32_t a;
    asm("{ .reg .u64 t; cvta.to.shared.u64 t, %1; cvt.u32.u64 %0, t; }" : "=r"(a) : "l"(p));
    return a;
}
__device__ __forceinline__ void cp_async16(uint32_t dst, const void* src) {
    asm volatile("cp.async.cg.shared.global [%0], [%1], 16;" :: "r"(dst), "l"(src) : "memory");
}
__device__ __forceinline__ void cp_commit() {
    asm volatile("cp.async.commit_group;" ::: "memory");
}
template <int N>
__device__ __forceinline__ void cp_wait() {
    asm volatile("cp.async.wait_group %0;" :: "n"(N) : "memory");
}
__device__ __forceinline__ void ldmatrix_x4(uint32_t* r, uint32_t addr) {
    asm volatile("ldmatrix.sync.aligned.m8n8.x4.shared.b16 {%0,%1,%2,%3}, [%4];"
                 : "=r"(r[0]), "=r"(r[1]), "=r"(r[2]), "=r"(r[3]) : "r"(addr));
}
__device__ __forceinline__ void ldmatrix_x2(uint32_t* r, uint32_t addr) {
    asm volatile("ldmatrix.sync.aligned.m8n8.x2.shared.b16 {%0,%1}, [%2];"
                 : "=r"(r[0]), "=r"(r[1]) : "r"(addr));
}
__device__ __forceinline__ void mma16816(float* c, const uint32_t* a, const uint32_t* b) {
    asm volatile(
        "mma.sync.aligned.m16n8k16.row.col.f32.bf16.bf16.f32 "
        "{%0,%1,%2,%3}, {%4,%5,%6,%7}, {%8,%9}, {%0,%1,%2,%3};"
        : "+f"(c[0]), "+f"(c[1]), "+f"(c[2]), "+f"(c[3])
        : "r"(a[0]), "r"(a[1]), "r"(a[2]), "r"(a[3]), "r"(b[0]), "r"(b[1]));
}
__device__ __forceinline__ float tanh_approx(float x) {
    float y;
    asm("tanh.approx.f32 %0, %1;" : "=f"(y) : "f"(x));
    return y;
}
__device__ __forceinline__ uint32_t pack_bf16x2(float lo, float hi) {
    __nv_bfloat162 p = __floats2bfloat162_rn(lo, hi);
    return *reinterpret_cast<uint32_t*>(&p);
}

// SW128 swizzle (Swizzle<3,4,3>) on tile-local byte offsets, rows = 128B.
#define SWZ(o) ((o) ^ (((o) >> 3) & 0x70))

// ---------------- kernel 1: f32 -> bf16 convert (Wk only) ----------------
__global__ void convert_kernel(const float* __restrict__ src, __nv_bfloat16* __restrict__ dst, long n4) {
    long i = (long)blockIdx.x * blockDim.x + threadIdx.x;
    if (i >= n4) return;
    float4 v = reinterpret_cast<const float4*>(src)[i];
    uint2 o;
    o.x = pack_bf16x2(v.x, v.y);
    o.y = pack_bf16x2(v.z, v.w);
    reinterpret_cast<uint2*>(dst)[i] = o;
}

// ---------------- kernel 2: qpk[b,a] = h_dec[b]·Wq[a] + Wq_b[a] + Wk_b[a] ----------------
__global__ void qpk_kernel(const float* __restrict__ hdec, const float* __restrict__ Wq,
                           const float* __restrict__ Wqb, const float* __restrict__ Wkb,
                           float* __restrict__ qpk) {
    int b = blockIdx.x;
    int a = threadIdx.x;  // 256
    __shared__ float h[DE];
    for (int e = threadIdx.x; e < DE; e += 256) h[e] = hdec[b * DE + e];
    __syncthreads();
    const float* w = Wq + (size_t)a * DE;
    float acc = 0.f;
#pragma unroll 8
    for (int e = 0; e < DE; e++) acc = fmaf(h[e], w[e], acc);
    qpk[b * DA + a] = acc + Wqb[a] + Wkb[a];
}

// ---------------- kernel 3: mma.sync GEMM (full N=256) + fused A-convert + score epilogue ----------------
// CTA tile: M=128, N=256 (ALL of DA — A tile loaded once), K=512 in 8 chunks of 64.
// 512 threads = 16 warps = 2(M) x 8(N), warp tile 64x32 (same per-warp regs as before).
// A: LDG f32 (hoisted before the wait), cvt->STS bf16 at loop bottom. B: cp.async bf16, double-buffered.
#define SM_PART   0                              // float s_part[8][128] = 4096 B
#define SM_V      4096                           // float sv[256]
#define SM_Q      5120                           // float sq[256]
#define SM_A(st)  (6144 + (st) * 16384)          // A stage: 128 rows x 128 B (bf16)
#define SM_B(st)  (38912 + (st) * 32768)         // B stage: 256 rows x 128 B (bf16)
#define GEMM_SMEM 104448

__global__ void __launch_bounds__(512, 1) gemm_score_kernel(
    const float* __restrict__ A,            // [B*T, 512] f32 (h_enc)
    const __nv_bfloat16* __restrict__ Bm,   // [256, 512] bf16 (Wk)
    const float* __restrict__ qpk,
    const float* __restrict__ v_w,
    float* __restrict__ scores) {           // [B*T]
    extern __shared__ char smem[];
    uint32_t sb = smem_u32(smem);
    int tid = threadIdx.x;
    int wid = tid >> 5, lane = tid & 31;
    int wm = wid >> 3, wn = wid & 7;
    int g = lane >> 2, tig = lane & 3;

    int bx = blockIdx.x;                   // b*32 + mt
    int b  = bx >> 5;
    int t0 = (bx & 31) << 7;
    size_t m0 = (size_t)bx * 128;

    if (tid < 256) {
        ((float*)(smem + SM_V))[tid] = v_w[tid];
        ((float*)(smem + SM_Q))[tid] = qpk[b * DA + tid];
    }

    const float* Abase = A + m0 * DE;

    // A geometry: chunk = 128 rows x 64 f32 = 2048 float4; 512 threads x 4 each.
    int arow0 = tid >> 4;                  // 0..31
    int acol4 = tid & 15;
    uint32_t asw[4];
#pragma unroll
    for (int i = 0; i < 4; i++)
        asw[i] = (uint32_t)SWZ((arow0 + i * 32) * 128 + acol4 * 8);

    auto ldgA4 = [&](int kc, float4* st) {
        const float4* src = (const float4*)(Abase + (size_t)kc * 64);
#pragma unroll
        for (int i = 0; i < 4; i++) {
            int row = arow0 + i * 32;
            st[i] = src[(size_t)row * 128 + acol4];
        }
    };
    auto stsA4 = [&](int stg, const float4* st) {
        char* dst = smem + SM_A(stg);
#pragma unroll
        for (int i = 0; i < 4; i++) {
            uint2 o;
            o.x = pack_bf16x2(st[i].x, st[i].y);
            o.y = pack_bf16x2(st[i].z, st[i].w);
            *reinterpret_cast<uint2*>(dst + asw[i]) = o;
        }
    };
    // B chunk = 256 rows x 64 bf16 = 2048 x 16B; 512 threads x 4 each.
    auto issueB = [&](int kc, int stg) {
        uint32_t bS = sb + SM_B(stg);
        const __nv_bfloat16* bb = Bm + kc * 64;
#pragma unroll
        for (int i = 0; i < 4; i++) {
            int c = tid + i * 512;
            int row = c >> 3, cc = c & 7;
            cp_async16(bS + SWZ(row * 128 + cc * 16), bb + (size_t)row * DE + cc * 8);
        }
        cp_commit();
    };

    float acc[4][4][4];
#pragma unroll
    for (int mi = 0; mi < 4; mi++)
#pragma unroll
        for (int ni = 0; ni < 4; ni++)
#pragma unroll
            for (int e = 0; e < 4; e++) acc[mi][ni][e] = 0.f;

    int arow = wm * 64 + (lane & 15);
    int acb  = lane >> 4;
    int brow = wn * 32 + (lane & 7);
    int bkb  = (lane >> 3) & 1;

    // ---- prologue: stage 0 staged ----
    {
        issueB(0, 0);
        float4 st[4];
        ldgA4(0, st);
        stsA4(0, st);
    }

#pragma unroll 1
    for (int kc = 0; kc < 8; kc++) {
        int cur = kc & 1, nxt = cur ^ 1;
        float4 st[4];
        if (kc < 7) ldgA4(kc + 1, st);    // register-only; hoisted before wait for extra cover
        cp_wait<0>();                      // drain B(cur)
        __syncthreads();                   // publish A/B(cur); reads of nxt retired
        if (kc < 7) issueB(kc + 1, nxt);   // safe post-sync

        uint32_t aS = sb + SM_A(cur), bS = sb + SM_B(cur);
#pragma unroll
        for (int ks = 0; ks < 4; ks++) {
            uint32_t af[4][4], bf_[4][2];
#pragma unroll
            for (int mi = 0; mi < 4; mi++)
                ldmatrix_x4(af[mi], aS + SWZ((arow + mi * 16) * 128 + ks * 32 + acb * 16));
#pragma unroll
            for (int ni = 0; ni < 4; ni++)
                ldmatrix_x2(bf_[ni], bS + SWZ((brow + ni * 8) * 128 + ks * 32 + bkb * 16));
#pragma unroll
            for (int mi = 0; mi < 4; mi++)
#pragma unroll
                for (int ni = 0; ni < 4; ni++)
                    mma16816(acc[mi][ni], af[mi], bf_[ni]);
        }
        if (kc < 7)
            stsA4(nxt, st);               // published by next iteration's sync
    }
    __syncthreads();                       // retire MMA smem reads before s_part reuse

    // ---- epilogue: score = sum over all 256 a of v*tanh(qpk + k) ----
    const float* sv = (const float*)(smem + SM_V);
    const float* sq = (const float*)(smem + SM_Q);
    float* s_part = (float*)(smem + SM_PART);

#pragma unroll
    for (int mi = 0; mi < 4; mi++) {
        float plo = 0.f, phi = 0.f;
#pragma unroll
        for (int ni = 0; ni < 4; ni++) {
            int n = wn * 32 + ni * 8 + tig * 2;
            float v0 = sv[n], v1 = sv[n + 1], q0 = sq[n], q1 = sq[n + 1];
            plo = fmaf(v0, tanh_approx(q0 + acc[mi][ni][0]), plo);
            plo = fmaf(v1, tanh_approx(q1 + acc[mi][ni][1]), plo);
            phi = fmaf(v0, tanh_approx(q0 + acc[mi][ni][2]), phi);
            phi = fmaf(v1, tanh_approx(q1 + acc[mi][ni][3]), phi);
        }
        plo += __shfl_xor_sync(~0u, plo, 1);
        plo += __shfl_xor_sync(~0u, plo, 2);
        phi += __shfl_xor_sync(~0u, phi, 1);
        phi += __shfl_xor_sync(~0u, phi, 2);
        if (tig == 0) {
            int row = wm * 64 + mi * 16 + g;
            s_part[wn * 128 + row] = plo;
            s_part[wn * 128 + row + 8] = phi;
        }
    }
    __syncthreads();
    if (tid < 128) {
        float s = 0.f;
#pragma unroll
        for (int j = 0; j < 8; j++) s += s_part[j * 128 + tid];
        scores[(size_t)b * TT + t0 + tid] = s;
    }
}

// ---------------- kernel 4: fused exp/mask + partial ctx over T-chunks ----------------
__global__ void ctx_part_kernel(const float* __restrict__ henc, const float* __restrict__ sc,
                                const void* __restrict__ maskp,
                                float* __restrict__ w, float* __restrict__ part,
                                float* __restrict__ psum) {
    int b = blockIdx.y;
    int tc = blockIdx.z;
    int e = blockIdx.x * 256 + threadIdx.x;
    int tid = threadIdx.x;
    __shared__ float ws[512];
    __shared__ float red[8];
    __shared__ int is_i32_sh;

    if (tid == 0) {
        // mask dtype auto-detect: int32 0/1 vs 1-byte bool (see R5 note)
        const uint32_t* mw = (const uint32_t*)maskp;
        int ok = 1;
        for (int i = 0; i < 64; i++)
            if (mw[i] > 1u) { ok = 0; break; }
        is_i32_sh = ok;
    }
    __syncthreads();
    int is_i32 = is_i32_sh;
    const int* mi32 = (const int*)maskp;
    const unsigned char* mu8 = (const unsigned char*)maskp;

    const float* s0 = sc + (size_t)b * TT + tc * 512;
    float local = 0.f;
    for (int t = tid; t < 512; t += 256) {
        size_t idx = (size_t)b * TT + tc * 512 + t;
        bool mv = is_i32 ? (mi32[idx] != 0) : (mu8[idx] != 0);
        float p = mv ? __expf(s0[t]) : 0.f;
        ws[t] = p;
        local += p;
    }
    __syncthreads();

    if (blockIdx.x == 0) {
        for (int t = tid; t < 512; t += 256) w[(size_t)b * TT + tc * 512 + t] = ws[t];
#pragma unroll
        for (int o = 16; o; o >>= 1) local += __shfl_xor_sync(~0u, local, o);
        if ((tid & 31) == 0) red[tid >> 5] = local;
        __syncthreads();
        if (tid == 0) {
            float s = 0.f;
#pragma unroll
            for (int i = 0; i < 8; i++) s += red[i];
            psum[tc * BB + b] = s;
        }
    }

    // 8 independent accumulators: deep FMA-chain break, high load MLP.
    const float* base = henc + (size_t)b * TT * DE + (size_t)tc * 512 * DE + e;
    float a0 = 0.f, a1 = 0.f, a2 = 0.f, a3 = 0.f, a4 = 0.f, a5 = 0.f, a6 = 0.f, a7 = 0.f;
#pragma unroll 2
    for (int t = 0; t < 512; t += 8) {
        a0 = fmaf(ws[t + 0], base[(size_t)(t + 0) * DE], a0);
        a1 = fmaf(ws[t + 1], base[(size_t)(t + 1) * DE], a1);
        a2 = fmaf(ws[t + 2], base[(size_t)(t + 2) * DE], a2);
        a3 = fmaf(ws[t + 3], base[(size_t)(t + 3) * DE], a3);
        a4 = fmaf(ws[t + 4], base[(size_t)(t + 4) * DE], a4);
        a5 = fmaf(ws[t + 5], base[(size_t)(t + 5) * DE], a5);
        a6 = fmaf(ws[t + 6], base[(size_t)(t + 6) * DE], a6);
        a7 = fmaf(ws[t + 7], base[(size_t)(t + 7) * DE], a7);
    }
    part[((size_t)tc * BB + b) * DE + e] = ((a0 + a1) + (a2 + a3)) + ((a4 + a5) + (a6 + a7));
}

// ---------------- kernel 5: finalize — normalize ctx and w ----------------
__global__ void finalize_kernel(const float* __restrict__ part, const float* __restrict__ psum,
                                float* __restrict__ ctx, float* __restrict__ w) {
    int b = blockIdx.x;
    int tid = threadIdx.x;  // 512
    __shared__ float invS;
    if (tid == 0) {
        float s = 0.f;
#pragma unroll
        for (int p = 0; p < 8; p++) s += psum[p * BB + b];
        invS = 1.f / s;
    }
    __syncthreads();
    float inv = invS;
    {
        float s = 0.f;
#pragma unroll
        for (int p = 0; p < 8; p++) s += part[((size_t)p * BB + b) * DE + tid];
        ctx[(size_t)b * DE + tid] = s * inv;
    }
    for (int t = tid; t < TT; t += 512)
        w[(size_t)b * TT + t] *= inv;
}

// ---------------- host launcher ----------------
extern "C" void kernel_launch(void* const* d_in, const int* in_sizes, int n_in,
                              void* d_out, int out_size) {
    const float* h_enc = (const float*)d_in[0];
    const float* h_dec = (const float*)d_in[1];
    const float* Wq_w  = (const float*)d_in[2];
    const float* Wq_b  = (const float*)d_in[3];
    const float* Wk_w  = (const float*)d_in[4];
    const float* Wk_b  = (const float*)d_in[5];
    const float* v_w   = (const float*)d_in[6];
    const void*  mask  = (const void*)d_in[7];

    float* out = (float*)d_out;
    float* ctx = out;                 // [B, 512]
    float* w   = out + BB * DE;       // [B, 4096]

    void *p_wk, *p_qpk, *p_sc, *p_part, *p_psum;
    cudaGetSymbolAddress(&p_wk, g_wk_bf);
    cudaGetSymbolAddress(&p_qpk, g_qpk);
    cudaGetSymbolAddress(&p_sc, g_scores);
    cudaGetSymbolAddress(&p_part, g_ctx_part);
    cudaGetSymbolAddress(&p_psum, g_psum);

    cudaFuncSetAttribute(gemm_score_kernel, cudaFuncAttributeMaxDynamicSharedMemorySize, GEMM_SMEM);

    convert_kernel<<<(DA * DE / 4) / 256, 256>>>(Wk_w, (__nv_bfloat16*)p_wk, DA * DE / 4);
    qpk_kernel<<<BB, 256>>>(h_dec, Wq_w, Wq_b, Wk_b, (float*)p_qpk);
    gemm_score_kernel<<<BB * 32, 512, GEMM_SMEM>>>(
        h_enc, (const __nv_bfloat16*)p_wk,
        (const float*)p_qpk, v_w, (float*)p_sc);
    ctx_part_kernel<<<dim3(2, BB, 8), 256>>>(h_enc, (const float*)p_sc, mask,
                                             w, (float*)p_part, (float*)p_psum);
    finalize_kernel<<<BB, 512>>>((const float*)p_part, (const float*)p_psum, ctx, w);
}